// round 16
// baseline (speedup 1.0000x reference)
#include <cuda_runtime.h>
#include <cuda_bf16.h>
#include <stdint.h>

// ---------------- problem constants -------------------------------------------
#define KB   32
#define KS   1024
#define KD   768
#define KNL  16
#define CK   64            // k-chunk (bf16 elements) -> 128 B/row (SW128 atom)
#define NCHUNK 12          // chunks per tile (768/64)
#define NTP  36            // tile-pairs per batch (8*9/2, it<=jt)
#define TPC  4             // tiles per CTA (persistent)
#define NG   (NCHUNK * TPC) // 48 chunks per CTA
#define NSTG 3             // cp.async ring stages
#define STB  (128 * 128)   // bytes per matrix-stage (128 rows x 128 B)
#define DSMEM (2 * NSTG * STB)   // 96 KB dynamic smem
#define SCALE_F (1.0f / (0.7f * 27.712812921102035f))   // 1/(T*sqrt(D))

// ---------------- device scratch ------------------------------------------------
__device__ __align__(256) __nv_bfloat16 g_feat[(size_t)KB * KS * KD];
__device__ int   g_lab[KB * KS];
__device__ int   g_cnt[KB][KNL];
// per-(batch, anchor-band, source-slot, anchor, {N,P,L}); each slot written once
__device__ float g_p3[KB * 8 * 8 * 128 * 3];
__device__ float g_part2[KB * 8];

// ---------------- kernel 1: fp32 -> bf16 conversion ------------------------------
__global__ void k_convert(const float* __restrict__ f) {
    size_t i  = (size_t)blockIdx.x * blockDim.x + threadIdx.x;
    size_t n4 = (size_t)KB * KS * KD / 4;
    if (i < n4) {
        float4 v = reinterpret_cast<const float4*>(f)[i];
        __nv_bfloat162 lo = __floats2bfloat162_rn(v.x, v.y);
        __nv_bfloat162 hi = __floats2bfloat162_rn(v.z, v.w);
        uint2 pk;
        pk.x = *reinterpret_cast<uint32_t*>(&lo);
        pk.y = *reinterpret_cast<uint32_t*>(&hi);
        reinterpret_cast<uint2*>(g_feat)[i] = pk;
    }
}

// ---------------- kernel 2: label dtype detect + widen + histogram ---------------
// Reference labels are .astype(jnp.int64); under JAX default x64-off that is
// silently int32. Detect per batch via the odd 32-bit words (int64 hi-words are
// always 0 for labels 0..15; int32 words are random labels, some nonzero with
// overwhelming probability). All indices stay < KB*KS words (safe either way).
__global__ void k_labels(const uint32_t* __restrict__ w) {
    __shared__ int cnt[KNL];
    const int b = blockIdx.x, t = threadIdx.x;
    int any = 0;
    for (int j = t; j < 512; j += 256) any |= (int)w[(b * 512 + j) * 2 + 1];
    const int is32 = __syncthreads_or(any);
    if (t < KNL) cnt[t] = 0;
    __syncthreads();
    for (int i = t; i < KS; i += 256) {
        int idx = b * KS + i;
        int v = is32 ? (int)w[idx] : (int)w[2 * idx];
        g_lab[idx] = v;
        atomicAdd(&cnt[v & (KNL - 1)], 1);
    }
    __syncthreads();
    if (t < KNL) g_cnt[b][t] = cnt[t];
}

// ---------------- PTX helpers -----------------------------------------------------
__device__ __forceinline__ void cp16(uint32_t dst, const void* src) {
    asm volatile("cp.async.cg.shared.global [%0], [%1], 16;\n"
                 :: "r"(dst), "l"(src) : "memory");
}
__device__ __forceinline__ void ldsm4(uint32_t* r, uint32_t addr) {
    asm volatile("ldmatrix.sync.aligned.m8n8.x4.shared.b16 {%0,%1,%2,%3}, [%4];\n"
                 : "=r"(r[0]), "=r"(r[1]), "=r"(r[2]), "=r"(r[3]) : "r"(addr));
}
__device__ __forceinline__ void mma_bf16(float* d, const uint32_t* a, const uint32_t* b) {
    asm volatile("mma.sync.aligned.m16n8k16.row.col.f32.bf16.bf16.f32 "
                 "{%0,%1,%2,%3}, {%4,%5,%6,%7}, {%8,%9}, {%0,%1,%2,%3};\n"
                 : "+f"(d[0]), "+f"(d[1]), "+f"(d[2]), "+f"(d[3])
                 : "r"(a[0]), "r"(a[1]), "r"(a[2]), "r"(a[3]),
                   "r"(b[0]), "r"(b[1]));
}
#define SWZ(o) ((o) ^ (((o) >> 3) & 0x70))   // SW128: conflict-free 16B-granule rows

// decode tile-pair index -> (batch, i0, j0)
__device__ __forceinline__ void decode_tp(int tp, int& b, int& it, int& jt) {
    b = tp / NTP;
    int rem = tp % NTP;
    it = 0;
    while (rem >= 8 - it) { rem -= 8 - it; ++it; }
    jt = it + rem;
}

// ---------------- kernel 3: persistent symmetric-tile GEMM + fused epilogue ------
// grid = KB*NTP/TPC = 288 CTAs; each CTA processes 4 tile-pairs sequentially with
// a CONTINUOUS 3-stage cp.async ring across tile boundaries: while tile t's last
// chunks compute / epilogue runs, tile t+1's first stages are already in flight.
// Loop invariant per global chunk g (0..47):
//   wait_group(1|0)  -> my stage-g copies done
//   __syncthreads    -> ALL threads' stage-g copies done; iter g-1 reads of
//                       buf (g-1)%3 finished
//   stage(g+2)       -> writes buf (g+2)%3 == (g-1)%3 (safe by barrier)
//   compute chunk g%12 of tile g/12
//   at g%12==11      -> fused epilogue for that tile (overlaps in-flight staging)
__global__ __launch_bounds__(256, 2) void k_main() {
    extern __shared__ __align__(128) unsigned char dyn[];
    __shared__ int   sjlab[128];
    __shared__ float sjrc[128];
    __shared__ float sred[128][2][3];
    __shared__ float scolp[4][128];

    const int tid  = threadIdx.x;
    const int lane = tid & 31;
    const int warp = tid >> 5;
    const int wm   = warp >> 1;     // 0..3 -> 32-row band
    const int wn   = warp & 1;      // 0..1 -> 64-col band
    const int tp0  = blockIdx.x * TPC;

    const uint32_t sA_u = (uint32_t)__cvta_generic_to_shared(dyn);
    const uint32_t sB_u = sA_u + NSTG * STB;

    float d[2][8][4];
    #pragma unroll
    for (int mi = 0; mi < 2; ++mi)
        #pragma unroll
        for (int ni = 0; ni < 8; ++ni)
            #pragma unroll
            for (int q = 0; q < 4; ++q) d[mi][ni][q] = 0.0f;

    auto stage = [&](int g) {
        int sb, sit, sjt;
        decode_tp(tp0 + g / NCHUNK, sb, sit, sjt);
        const __nv_bfloat16* fb = g_feat + (size_t)sb * KS * KD;
        const int c  = g % NCHUNK;
        const int i0 = sit * 128, j0 = sjt * 128;
        const uint32_t so = (uint32_t)(g % NSTG) * STB;
        #pragma unroll
        for (int q = 0; q < 4; ++q) {      // A: 1024 granules / 256 thr
            int gi = tid + q * 256;
            int row = gi >> 3, seg = gi & 7;
            uint32_t off = (uint32_t)row * 128 + seg * 16;
            cp16(sA_u + so + SWZ(off), fb + (size_t)(i0 + row) * KD + c * CK + seg * 8);
        }
        #pragma unroll
        for (int q = 0; q < 4; ++q) {      // B
            int gi = tid + q * 256;
            int row = gi >> 3, seg = gi & 7;
            uint32_t off = (uint32_t)row * 128 + seg * 16;
            cp16(sB_u + so + SWZ(off), fb + (size_t)(j0 + row) * KD + c * CK + seg * 8);
        }
        asm volatile("cp.async.commit_group;\n" ::: "memory");
    };

    stage(0);
    stage(1);

    #pragma unroll 1
    for (int g = 0; g < NG; ++g) {
        if (g < NG - 1) asm volatile("cp.async.wait_group 1;\n" ::: "memory");
        else            asm volatile("cp.async.wait_group 0;\n" ::: "memory");
        __syncthreads();
        if (g + 2 < NG) stage(g + 2);

        const uint32_t bA = sA_u + (uint32_t)(g % NSTG) * STB;
        const uint32_t bB = sB_u + (uint32_t)(g % NSTG) * STB;
        #pragma unroll 2
        for (int ks = 0; ks < 4; ++ks) {
            uint32_t afr[2][4];
            #pragma unroll
            for (int mi = 0; mi < 2; ++mi) {
                int row = wm * 32 + mi * 16 + (lane & 7) + ((lane >> 3) & 1) * 8;
                uint32_t off = (uint32_t)row * 128 + ks * 32 + (lane >> 4) * 16;
                ldsm4(afr[mi], bA + SWZ(off));
            }
            uint32_t bfr[4][4];
            #pragma unroll
            for (int pi = 0; pi < 4; ++pi) {
                int t   = lane >> 3;
                int row = wn * 64 + (2 * pi + (t >> 1)) * 8 + (lane & 7);
                uint32_t off = (uint32_t)row * 128 + ks * 32 + (t & 1) * 16;
                ldsm4(bfr[pi], bB + SWZ(off));
            }
            #pragma unroll
            for (int mi = 0; mi < 2; ++mi)
                #pragma unroll
                for (int ni = 0; ni < 8; ++ni)
                    mma_bf16(d[mi][ni], afr[mi], &bfr[ni >> 1][(ni & 1) * 2]);
        }

        if ((g % NCHUNK) != NCHUNK - 1) continue;

        // ================= fused epilogue for tile g/NCHUNK =====================
        int b, it, jt;
        decode_tp(tp0 + g / NCHUNK, b, it, jt);
        const int i0 = it * 128, j0 = jt * 128;
        const bool offdiag = (jt != it);
        const int* lb = g_lab + b * KS;

        // column metadata (sjlab/sjrc last read at previous epilogue's scolp/sred
        // phase; the mainloop barriers since then make this write safe)
        if (tid < 128) {
            int l = lb[j0 + tid];
            sjlab[tid] = l;
            int nnj = KS - g_cnt[b][l & (KNL - 1)];
            sjrc[tid] = (nnj > 0) ? (SCALE_F / (float)nnj) : 0.0f;
        }
        // row-anchor metadata (4 rows per thread: r = mi*2 + h)
        int   rlab[4], rig[4];
        float rc[4];
        #pragma unroll
        for (int mi = 0; mi < 2; ++mi)
            #pragma unroll
            for (int h = 0; h < 2; ++h) {
                int r  = mi * 2 + h;
                int ig = i0 + wm * 32 + mi * 16 + h * 8 + (lane >> 2);
                int l  = lb[ig];
                rig[r]  = ig;
                rlab[r] = l;
                int nn  = KS - g_cnt[b][l & (KNL - 1)];
                rc[r]   = (nn > 0) ? (SCALE_F / (float)nn) : 0.0f;
            }
        __syncthreads();

        float accN[4] = {0, 0, 0, 0};
        float accP[4] = {0, 0, 0, 0};
        float accL[4] = {0, 0, 0, 0};
        float cAcc[16];
        #pragma unroll
        for (int t = 0; t < 16; ++t) cAcc[t] = 0.0f;

        #pragma unroll
        for (int ni = 0; ni < 8; ++ni)
            #pragma unroll
            for (int q = 0; q < 2; ++q) {
                int jl  = wn * 64 + ni * 8 + ((lane & 3) << 1) + q;
                int jlb = sjlab[jl];
                int jg  = j0 + jl;
                float rcj = sjrc[jl];
                #pragma unroll
                for (int mi = 0; mi < 2; ++mi)
                    #pragma unroll
                    for (int h = 0; h < 2; ++h) {
                        int r = mi * 2 + h;
                        float dv = d[mi][ni][h * 2 + q];
                        bool same = (jlb == rlab[r]);
                        // exp(x), |x| <= ~0.01: cubic Taylor, rel err ~2e-10
                        float x = dv * rc[r];
                        float p = fmaf(x, fmaf(x, fmaf(x, 0.16666667f, 0.5f), 1.0f), 1.0f);
                        if (!same) {
                            accN[r] += p;
                            if (offdiag) {
                                float xc = dv * rcj;
                                cAcc[ni * 2 + q] +=
                                    fmaf(xc, fmaf(xc, fmaf(xc, 0.16666667f, 0.5f), 1.0f), 1.0f);
                            }
                        } else if (jg > rig[r]) {
                            accP[r] += dv; accL[r] += 1.0f;
                        }
                        d[mi][ni][h * 2 + q] = 0.0f;   // reset for next tile
                    }
            }

        // row reduction: 4 lanes share a row
        #pragma unroll
        for (int r = 0; r < 4; ++r) {
            #pragma unroll
            for (int off = 1; off < 4; off <<= 1) {
                accN[r] += __shfl_xor_sync(0xffffffffu, accN[r], off);
                accP[r] += __shfl_xor_sync(0xffffffffu, accP[r], off);
                accL[r] += __shfl_xor_sync(0xffffffffu, accL[r], off);
            }
        }
        // col reduction: 8 lane-groups share a col
        if (offdiag) {
            #pragma unroll
            for (int t = 0; t < 16; ++t) {
                float v = cAcc[t];
                v += __shfl_xor_sync(0xffffffffu, v, 4);
                v += __shfl_xor_sync(0xffffffffu, v, 8);
                v += __shfl_xor_sync(0xffffffffu, v, 16);
                cAcc[t] = v;
            }
        }
        __syncthreads();
        if ((lane & 3) == 0) {
            #pragma unroll
            for (int r = 0; r < 4; ++r) {
                int iloc = wm * 32 + (r >> 1) * 16 + (r & 1) * 8 + (lane >> 2);
                sred[iloc][wn][0] = accN[r];
                sred[iloc][wn][1] = accP[r];
                sred[iloc][wn][2] = accL[r];
            }
        }
        if (offdiag && (lane >> 2) == 0) {
            #pragma unroll
            for (int ni = 0; ni < 8; ++ni)
                #pragma unroll
                for (int q = 0; q < 2; ++q) {
                    int jl = wn * 64 + ni * 8 + (lane & 3) * 2 + q;
                    scolp[wm][jl] = cAcc[ni * 2 + q];
                }
        }
        __syncthreads();

        if (tid < 128) {
            float* rs = &g_p3[((((size_t)b * 8 + it) * 8 + jt) * 128 + tid) * 3];
            rs[0] = sred[tid][0][0] + sred[tid][1][0];
            rs[1] = sred[tid][0][1] + sred[tid][1][1];
            rs[2] = sred[tid][0][2] + sred[tid][1][2];
            if (offdiag) {
                float* cs = &g_p3[((((size_t)b * 8 + jt) * 8 + it) * 128 + tid) * 3];
                cs[0] = scolp[0][tid] + scolp[1][tid] + scolp[2][tid] + scolp[3][tid];
                cs[1] = 0.0f;
                cs[2] = 0.0f;
            }
        }
    }
}

// ---------------- kernel 4: per-anchor loss, one block per (batch, band) ---------
__global__ void k_loss() {
    __shared__ float s[128];
    const int b = blockIdx.x >> 3, band = blockIdx.x & 7;
    const int a = threadIdx.x;
    float N = 0.0f, P = 0.0f, L = 0.0f;
    #pragma unroll
    for (int sl = 0; sl < 8; ++sl) {
        const float* p = &g_p3[((((size_t)b * 8 + band) * 8 + sl) * 128 + a) * 3];
        N += p[0]; P += p[1]; L += p[2];
    }
    int l  = g_lab[b * KS + band * 128 + a];
    int gs = g_cnt[b][l & (KNL - 1)];
    int nn = KS - gs;
    float per = (nn > 0) ? (-(P * SCALE_F - L * logf(N)) / (float)gs) : 0.0f;
    s[a] = per;
    __syncthreads();
    #pragma unroll 1
    for (int st = 64; st > 0; st >>= 1) {
        if (a < st) s[a] += s[a + st];
        __syncthreads();
    }
    if (a == 0) g_part2[blockIdx.x] = s[0];
}

// ---------------- kernel 5: deterministic final reduce ----------------------------
__global__ void k_final(float* out) {
    __shared__ float s[256];
    int t = threadIdx.x;
    s[t] = g_part2[t];
    __syncthreads();
    #pragma unroll 1
    for (int st = 128; st > 0; st >>= 1) {
        if (t < st) s[t] += s[t + st];
        __syncthreads();
    }
    if (t == 0) out[0] = s[0] / (float)KS;
}

// ---------------- launcher ---------------------------------------------------------
extern "C" void kernel_launch(void* const* d_in, const int* in_sizes, int n_in,
                              void* d_out, int out_size) {
    (void)n_in; (void)out_size;
    const void* p0 = d_in[0];
    const void* p1 = d_in[1];
    const float*    feat;
    const uint32_t* labw;
    if (in_sizes[0] >= in_sizes[1]) { feat = (const float*)p0; labw = (const uint32_t*)p1; }
    else                            { feat = (const float*)p1; labw = (const uint32_t*)p0; }
    float* out = (float*)d_out;

    static int attr_set = 0;
    if (!attr_set) {
        cudaFuncSetAttribute(k_main, cudaFuncAttributeMaxDynamicSharedMemorySize, DSMEM);
        attr_set = 1;
    }

    size_t n4 = (size_t)KB * KS * KD / 4;
    k_convert<<<(unsigned)((n4 + 255) / 256), 256>>>(feat);
    k_labels<<<KB, 256>>>(labw);
    k_main<<<KB * NTP / TPC, 256, DSMEM>>>();
    k_loss<<<KB * 8, 128>>>();
    k_final<<<1, 256>>>(out);
}

// round 17
// speedup vs baseline: 1.0526x; 1.0526x over previous
#include <cuda_runtime.h>
#include <cuda_bf16.h>
#include <stdint.h>

// ---------------- problem constants -------------------------------------------
#define KB   32
#define KS   1024
#define KD   768
#define KNL  16
#define CK   64            // k-chunk (bf16 elements) -> 128 B/row (SW128 atom)
#define NCHUNK (KD / CK)   // 12
#define NTP  36            // tile-pairs per batch (8*9/2, it<=jt)
#define NSTG 3             // cp.async ring stages
#define STB  (128 * 128)   // bytes per matrix-stage (128 rows x 128 B)
#define DSMEM (2 * NSTG * STB)   // 96 KB dynamic smem
#define SCALE_F (1.0f / (0.7f * 27.712812921102035f))   // 1/(T*sqrt(D))

// ---------------- device scratch ------------------------------------------------
__device__ __align__(256) __nv_bfloat16 g_feat[(size_t)KB * KS * KD];
__device__ int   g_lab[KB * KS];
__device__ int   g_cnt[KB][KNL];
// per-(batch, anchor-band, source-slot, anchor, {N,P,L}); each slot written once
__device__ float g_p3[KB * 8 * 8 * 128 * 3];
__device__ float g_part2[64];

// ---------------- kernel 1: fp32 -> bf16 conversion ------------------------------
__global__ void k_convert(const float* __restrict__ f) {
    size_t i  = (size_t)blockIdx.x * blockDim.x + threadIdx.x;
    size_t n4 = (size_t)KB * KS * KD / 4;
    if (i < n4) {
        float4 v = reinterpret_cast<const float4*>(f)[i];
        __nv_bfloat162 lo = __floats2bfloat162_rn(v.x, v.y);
        __nv_bfloat162 hi = __floats2bfloat162_rn(v.z, v.w);
        uint2 pk;
        pk.x = *reinterpret_cast<uint32_t*>(&lo);
        pk.y = *reinterpret_cast<uint32_t*>(&hi);
        reinterpret_cast<uint2*>(g_feat)[i] = pk;
    }
}

// ---------------- kernel 2: label dtype detect + widen + histogram ---------------
// Reference labels are .astype(jnp.int64); under JAX default x64-off that is
// silently int32. Detect per batch via the odd 32-bit words (int64 hi-words are
// always 0 for labels 0..15; int32 words are random labels, some nonzero with
// overwhelming probability). All indices stay < KB*KS words (safe either way).
__global__ void k_labels(const uint32_t* __restrict__ w) {
    __shared__ int cnt[KNL];
    const int b = blockIdx.x, t = threadIdx.x;
    int any = 0;
    for (int j = t; j < 512; j += 256) any |= (int)w[(b * 512 + j) * 2 + 1];
    const int is32 = __syncthreads_or(any);
    if (t < KNL) cnt[t] = 0;
    __syncthreads();
    for (int i = t; i < KS; i += 256) {
        int idx = b * KS + i;
        int v = is32 ? (int)w[idx] : (int)w[2 * idx];
        g_lab[idx] = v;
        atomicAdd(&cnt[v & (KNL - 1)], 1);
    }
    __syncthreads();
    if (t < KNL) g_cnt[b][t] = cnt[t];
}

// ---------------- PTX helpers -----------------------------------------------------
__device__ __forceinline__ void cp16(uint32_t dst, const void* src) {
    asm volatile("cp.async.cg.shared.global [%0], [%1], 16;\n"
                 :: "r"(dst), "l"(src) : "memory");
}
__device__ __forceinline__ void ldsm4(uint32_t* r, uint32_t addr) {
    asm volatile("ldmatrix.sync.aligned.m8n8.x4.shared.b16 {%0,%1,%2,%3}, [%4];\n"
                 : "=r"(r[0]), "=r"(r[1]), "=r"(r[2]), "=r"(r[3]) : "r"(addr));
}
__device__ __forceinline__ void mma_bf16(float* d, const uint32_t* a, const uint32_t* b) {
    asm volatile("mma.sync.aligned.m16n8k16.row.col.f32.bf16.bf16.f32 "
                 "{%0,%1,%2,%3}, {%4,%5,%6,%7}, {%8,%9}, {%0,%1,%2,%3};\n"
                 : "+f"(d[0]), "+f"(d[1]), "+f"(d[2]), "+f"(d[3])
                 : "r"(a[0]), "r"(a[1]), "r"(a[2]), "r"(a[3]),
                   "r"(b[0]), "r"(b[1]));
}
#define SWZ(o) ((o) ^ (((o) >> 3) & 0x70))   // SW128: conflict-free 16B-granule rows

// ---------------- kernel 3: symmetric-tile GEMM + fused SupCon epilogue ----------
// grid = KB*36 CTAs: (batch b, tile-pair it<=jt). 128x128x768 bf16 GEMM per CTA.
// 3-stage cp.async ring, K=64 chunks, ONE __syncthreads per chunk:
//   wait_group(1|0)  -> my stage-c copies done
//   __syncthreads    -> ALL threads' stage-c copies done; proves iter c-1 reads
//                       of buf (c-1)%3 finished
//   stage(c+2)       -> writes buf (c+2)%3 == (c-1)%3 (safe by barrier)
//   compute(c)       -> reads buf c%3 (published by wait+barrier)
// Diagonal tiles (it==jt): A and B are the same 16 KB -> skip B staging and
// read B fragments from the A buffer (halves cp.async/L2 traffic for 8/36 tiles).
__global__ __launch_bounds__(256, 2) void k_main() {
    extern __shared__ __align__(128) unsigned char dyn[];
    __shared__ int   sjlab[128];
    __shared__ float sjrc[128];
    __shared__ float sred[128][2][3];
    __shared__ float scolp[4][128];

    const int tid  = threadIdx.x;
    const int lane = tid & 31;
    const int warp = tid >> 5;
    const int wm   = warp >> 1;     // 0..3 -> 32-row band
    const int wn   = warp & 1;      // 0..1 -> 64-col band

    // decode (b, it, jt)
    const int b = blockIdx.x / NTP;
    int rem = blockIdx.x % NTP;
    int it = 0;
    while (rem >= 8 - it) { rem -= 8 - it; ++it; }
    const int jt = it + rem;
    const int i0 = it * 128;
    const int j0 = jt * 128;
    const bool offdiag = (jt != it);

    const uint32_t sA_u = (uint32_t)__cvta_generic_to_shared(dyn);
    const uint32_t sB_u = offdiag ? (sA_u + NSTG * STB) : sA_u;   // diag: alias A
    const __nv_bfloat16* fb = g_feat + (size_t)b * KS * KD;
    const int*           lb = g_lab  + b * KS;

    // row-anchor metadata (4 rows per thread: r = mi*2 + h)
    int   rlab[4];
    float rc[4];
    #pragma unroll
    for (int mi = 0; mi < 2; ++mi)
        #pragma unroll
        for (int h = 0; h < 2; ++h) {
            int r  = mi * 2 + h;
            int ig = i0 + wm * 32 + mi * 16 + h * 8 + (lane >> 2);
            int l  = lb[ig];
            rlab[r] = l;
            int nn  = KS - g_cnt[b][l & (KNL - 1)];
            rc[r]   = (nn > 0) ? (SCALE_F / (float)nn) : 0.0f;
        }
    if (tid < 128) {
        int l = lb[j0 + tid];
        sjlab[tid] = l;
        int nnj = KS - g_cnt[b][l & (KNL - 1)];
        sjrc[tid] = (nnj > 0) ? (SCALE_F / (float)nnj) : 0.0f;
    }

    float d[2][8][4];
    #pragma unroll
    for (int mi = 0; mi < 2; ++mi)
        #pragma unroll
        for (int ni = 0; ni < 8; ++ni)
            #pragma unroll
            for (int q = 0; q < 4; ++q) d[mi][ni][q] = 0.0f;

    auto stage = [&](int c) {
        const uint32_t so = (uint32_t)(c % NSTG) * STB;
        #pragma unroll
        for (int q = 0; q < 4; ++q) {      // A: 1024 granules / 256 thr
            int gi = tid + q * 256;
            int row = gi >> 3, seg = gi & 7;
            uint32_t off = (uint32_t)row * 128 + seg * 16;
            cp16(sA_u + so + SWZ(off), fb + (size_t)(i0 + row) * KD + c * CK + seg * 8);
        }
        if (offdiag) {
            #pragma unroll
            for (int q = 0; q < 4; ++q) {  // B (skipped on diagonal tiles)
                int gi = tid + q * 256;
                int row = gi >> 3, seg = gi & 7;
                uint32_t off = (uint32_t)row * 128 + seg * 16;
                cp16(sB_u + so + SWZ(off), fb + (size_t)(j0 + row) * KD + c * CK + seg * 8);
            }
        }
        asm volatile("cp.async.commit_group;\n" ::: "memory");
    };

    stage(0);
    stage(1);

    #pragma unroll 1
    for (int c = 0; c < NCHUNK; ++c) {
        // stage c resident for THIS thread (groups c, c+1 in flight)
        if (c < NCHUNK - 1) asm volatile("cp.async.wait_group 1;\n" ::: "memory");
        else                asm volatile("cp.async.wait_group 0;\n" ::: "memory");
        __syncthreads();                   // stage c resident for ALL threads;
                                           // iter c-1 reads of buf (c-1)%3 done
        if (c + 2 < NCHUNK) stage(c + 2);  // writes buf (c-1)%3 -> safe

        const uint32_t bA = sA_u + (uint32_t)(c % NSTG) * STB;
        const uint32_t bB = sB_u + (uint32_t)(c % NSTG) * STB;
        #pragma unroll 2
        for (int ks = 0; ks < 4; ++ks) {
            uint32_t afr[2][4];
            #pragma unroll
            for (int mi = 0; mi < 2; ++mi) {
                int row = wm * 32 + mi * 16 + (lane & 7) + ((lane >> 3) & 1) * 8;
                uint32_t off = (uint32_t)row * 128 + ks * 32 + (lane >> 4) * 16;
                ldsm4(afr[mi], bA + SWZ(off));
            }
            uint32_t bfr[4][4];
            #pragma unroll
            for (int pi = 0; pi < 4; ++pi) {
                int t   = lane >> 3;
                int row = wn * 64 + (2 * pi + (t >> 1)) * 8 + (lane & 7);
                uint32_t off = (uint32_t)row * 128 + ks * 32 + (t & 1) * 16;
                ldsm4(bfr[pi], bB + SWZ(off));
            }
            #pragma unroll
            for (int mi = 0; mi < 2; ++mi)
                #pragma unroll
                for (int ni = 0; ni < 8; ++ni)
                    mma_bf16(d[mi][ni], afr[mi], &bfr[ni >> 1][(ni & 1) * 2]);
        }
    }

    // ---- fused epilogue: row view + (offdiag) column view --------------------
    float accN[4] = {0, 0, 0, 0};
    float accP[4] = {0, 0, 0, 0};
    float accL[4] = {0, 0, 0, 0};
    float cAcc[16];
    #pragma unroll
    for (int t = 0; t < 16; ++t) cAcc[t] = 0.0f;

    #pragma unroll
    for (int ni = 0; ni < 8; ++ni)
        #pragma unroll
        for (int q = 0; q < 2; ++q) {
            int jl  = wn * 64 + ni * 8 + ((lane & 3) << 1) + q;
            int jlb = sjlab[jl];
            int jg  = j0 + jl;
            float rcj = sjrc[jl];
            #pragma unroll
            for (int mi = 0; mi < 2; ++mi)
                #pragma unroll
                for (int h = 0; h < 2; ++h) {
                    int r = mi * 2 + h;
                    float dv = d[mi][ni][h * 2 + q];
                    bool same = (jlb == rlab[r]);
                    // exp(x), |x| <= ~0.01: cubic Taylor, rel err ~2e-10
                    float x = dv * rc[r];
                    float p = fmaf(x, fmaf(x, fmaf(x, 0.16666667f, 0.5f), 1.0f), 1.0f);
                    if (!same) {
                        accN[r] += p;
                        if (offdiag) {
                            float xc = dv * rcj;
                            cAcc[ni * 2 + q] +=
                                fmaf(xc, fmaf(xc, fmaf(xc, 0.16666667f, 0.5f), 1.0f), 1.0f);
                        }
                    } else {
                        int ig = i0 + wm * 32 + mi * 16 + h * 8 + (lane >> 2);
                        if (jg > ig) { accP[r] += dv; accL[r] += 1.0f; }
                    }
                }
        }

    // ---- row reduction: 4 lanes share a row ------------------------------------
    #pragma unroll
    for (int r = 0; r < 4; ++r) {
        #pragma unroll
        for (int off = 1; off < 4; off <<= 1) {
            accN[r] += __shfl_xor_sync(0xffffffffu, accN[r], off);
            accP[r] += __shfl_xor_sync(0xffffffffu, accP[r], off);
            accL[r] += __shfl_xor_sync(0xffffffffu, accL[r], off);
        }
    }
    // ---- col reduction: 8 lane-groups share a col -------------------------------
    if (offdiag) {
        #pragma unroll
        for (int t = 0; t < 16; ++t) {
            float v = cAcc[t];
            v += __shfl_xor_sync(0xffffffffu, v, 4);
            v += __shfl_xor_sync(0xffffffffu, v, 8);
            v += __shfl_xor_sync(0xffffffffu, v, 16);
            cAcc[t] = v;
        }
    }
    __syncthreads();
    if ((lane & 3) == 0) {
        #pragma unroll
        for (int r = 0; r < 4; ++r) {
            int iloc = wm * 32 + (r >> 1) * 16 + (r & 1) * 8 + (lane >> 2);
            sred[iloc][wn][0] = accN[r];
            sred[iloc][wn][1] = accP[r];
            sred[iloc][wn][2] = accL[r];
        }
    }
    if (offdiag && (lane >> 2) == 0) {
        #pragma unroll
        for (int ni = 0; ni < 8; ++ni)
            #pragma unroll
            for (int q = 0; q < 2; ++q) {
                int jl = wn * 64 + ni * 8 + (lane & 3) * 2 + q;
                scolp[wm][jl] = cAcc[ni * 2 + q];
            }
    }
    __syncthreads();

    if (tid < 128) {
        float* rs = &g_p3[((((size_t)b * 8 + it) * 8 + jt) * 128 + tid) * 3];
        rs[0] = sred[tid][0][0] + sred[tid][1][0];
        rs[1] = sred[tid][0][1] + sred[tid][1][1];
        rs[2] = sred[tid][0][2] + sred[tid][1][2];
        if (offdiag) {
            float* cs = &g_p3[((((size_t)b * 8 + jt) * 8 + it) * 128 + tid) * 3];
            cs[0] = scolp[0][tid] + scolp[1][tid] + scolp[2][tid] + scolp[3][tid];
            cs[1] = 0.0f;
            cs[2] = 0.0f;
        }
    }
}

// ---------------- kernel 4: per-anchor loss, 64 blocks x 512 threads -------------
__global__ void k_loss() {
    __shared__ float s[16];
    const int t   = threadIdx.x;
    const int idx = blockIdx.x * 512 + t;       // global anchor 0..32767
    const int b   = idx >> 10;
    const int a10 = idx & 1023;
    const int band = a10 >> 7, a = a10 & 127;
    float N = 0.0f, P = 0.0f, L = 0.0f;
    #pragma unroll
    for (int sl = 0; sl < 8; ++sl) {
        const float* p = &g_p3[((((size_t)b * 8 + band) * 8 + sl) * 128 + a) * 3];
        N += p[0]; P += p[1]; L += p[2];
    }
    int l  = g_lab[idx];
    int gs = g_cnt[b][l & (KNL - 1)];
    int nn = KS - gs;
    float per = (nn > 0) ? (-(P * SCALE_F - L * logf(N)) / (float)gs) : 0.0f;
    // deterministic fixed-tree reduction: warp shfl -> smem -> warp 0
    #pragma unroll
    for (int off = 16; off > 0; off >>= 1)
        per += __shfl_xor_sync(0xffffffffu, per, off);
    if ((t & 31) == 0) s[t >> 5] = per;
    __syncthreads();
    if (t < 32) {
        float v = (t < 16) ? s[t] : 0.0f;
        #pragma unroll
        for (int off = 8; off > 0; off >>= 1)
            v += __shfl_xor_sync(0xffffffffu, v, off);
        if (t == 0) g_part2[blockIdx.x] = v;
    }
}

// ---------------- kernel 5: deterministic final reduce ----------------------------
__global__ void k_final(float* out) {
    __shared__ float s[64];
    int t = threadIdx.x;
    s[t] = g_part2[t];
    __syncthreads();
    #pragma unroll 1
    for (int st = 32; st > 0; st >>= 1) {
        if (t < st) s[t] += s[t + st];
        __syncthreads();
    }
    if (t == 0) out[0] = s[0] / (float)KS;
}

// ---------------- launcher ---------------------------------------------------------
extern "C" void kernel_launch(void* const* d_in, const int* in_sizes, int n_in,
                              void* d_out, int out_size) {
    (void)n_in; (void)out_size;
    const void* p0 = d_in[0];
    const void* p1 = d_in[1];
    const float*    feat;
    const uint32_t* labw;
    if (in_sizes[0] >= in_sizes[1]) { feat = (const float*)p0; labw = (const uint32_t*)p1; }
    else                            { feat = (const float*)p1; labw = (const uint32_t*)p0; }
    float* out = (float*)d_out;

    static int attr_set = 0;
    if (!attr_set) {
        cudaFuncSetAttribute(k_main, cudaFuncAttributeMaxDynamicSharedMemorySize, DSMEM);
        attr_set = 1;
    }

    size_t n4 = (size_t)KB * KS * KD / 4;
    k_convert<<<(unsigned)((n4 + 511) / 512), 512>>>(feat);
    k_labels<<<KB, 256>>>(labw);
    k_main<<<KB * NTP, 256, DSMEM>>>();
    k_loss<<<64, 512>>>();
    k_final<<<1, 64>>>(out);
}